// round 15
// baseline (speedup 1.0000x reference)
#include <cuda_runtime.h>
#include <cuda_bf16.h>
#include <cstdint>
#include <math.h>

#define B_   128
#define T_   256
#define L_   16
#define DW_  300
#define DC_  100
#define HC_  100
#define H_   300
#define NT_  3
#define NV_  101          // char vocab rows (NC+1)
#define EMB_ 500          // DW + 2*HC
#define KP_  512          // padded K for x-proj MMA
#define KR_  304          // padded K for recurrent word MMA
#define CKS  112          // padded K for char recurrent MMA (100 -> 7x16)
#define CKSTR 120         // smem row stride (bf16) for char MMA tiles
#define GW_  1200         // 4*H
#define GC_  400          // 4*HC
#define BT_  32768        // B*T
#define GRP_BLK 15        // u-tile blocks per (b,dir) barrier group

// ---------------- static device scratch (no runtime allocation) ----------------
__device__ __align__(16) float g_zx[2][BT_ * GW_];       // x-projection (gate-permuted)
__device__ __align__(16) float g_bwp[2][GW_];            // permuted word bias
__device__ __align__(16) float g_zcv[2][NV_ * GC_];      // char vocab x-proj
__device__ __align__(16) float g_c[2][B_ * H_];          // word cell state (output)
// bf16 hi/lo activations for the x-proj MMA: word emb (k_embed) + char rep (k_char)
__device__ __align__(16) __nv_bfloat16 g_Ahi[BT_ * KP_];
__device__ __align__(16) __nv_bfloat16 g_Alo[BT_ * KP_];
__device__ __align__(16) __nv_bfloat16 g_Bhi[2][GW_ * KP_];
__device__ __align__(16) __nv_bfloat16 g_Blo[2][GW_ * KP_];
// bf16 hi/lo of recurrent word W, row jp, K-major padded to 304
__device__ __align__(16) __nv_bfloat16 g_Wrhi[2][GW_ * KR_];
__device__ __align__(16) __nv_bfloat16 g_Wrlo[2][GW_ * KR_];
// bf16 hi/lo of char recurrent W, row jp (gate-permuted), K-major padded to 112
__device__ __align__(16) __nv_bfloat16 g_Wchi[2][GC_ * CKS];
__device__ __align__(16) __nv_bfloat16 g_Wclo[2][GC_ * CKS];
// word h as bf16 hi/lo (double-buffered by parity): [parity][dir][B*304]
__device__ __align__(16) __nv_bfloat16 g_hhi[2][2][B_ * KR_];
__device__ __align__(16) __nv_bfloat16 g_hlo[2][2][B_ * KR_];
// per-group grid barrier state (8 groups of 15 blocks)
__device__ volatile unsigned g_barc8[8];
__device__ volatile unsigned g_barp8[8];

__device__ __forceinline__ float sigf(float x) {
    return __fdividef(1.f, 1.f + __expf(-x));
}
__device__ __forceinline__ float tanhfast(float x) {
    x = fminf(fmaxf(x, -15.f), 15.f);
    float e = __expf(2.f * x);
    return __fdividef(e - 1.f, e + 1.f);
}

__device__ __forceinline__ void gbar_grp(int g, unsigned& phase) {
    __threadfence();
    __syncthreads();
    if (threadIdx.x == 0) {
        unsigned old = atomicAdd((unsigned*)&g_barc8[g], 1u);
        if (old == GRP_BLK - 1u) {
            g_barc8[g] = 0u;
            __threadfence();
            atomicAdd((unsigned*)&g_barp8[g], 1u);
        } else {
            while (g_barp8[g] <= phase) { }
        }
    }
    __syncthreads();
    phase++;
}

// ---------------- warp-level MMA helpers ----------------
__device__ __forceinline__ uint32_t smem_u32(const void* p) {
    uint32_t a;
    asm("{ .reg .u64 t; cvta.to.shared.u64 t, %1; cvt.u32.u64 %0, t; }" : "=r"(a) : "l"(p));
    return a;
}
#define LDSM_X4(r0, r1, r2, r3, addr) \
    asm volatile("ldmatrix.sync.aligned.m8n8.x4.shared.b16 {%0,%1,%2,%3}, [%4];" \
                 : "=r"(r0), "=r"(r1), "=r"(r2), "=r"(r3) : "r"(addr))
#define LDSM_X2(r0, r1, addr) \
    asm volatile("ldmatrix.sync.aligned.m8n8.x2.shared.b16 {%0,%1}, [%2];" \
                 : "=r"(r0), "=r"(r1) : "r"(addr))
#define MMA16816(c, a, b) \
    asm volatile("mma.sync.aligned.m16n8k16.row.col.f32.bf16.bf16.f32 " \
                 "{%0,%1,%2,%3}, {%4,%5,%6,%7}, {%8,%9}, {%0,%1,%2,%3};" \
                 : "+f"((c)[0]), "+f"((c)[1]), "+f"((c)[2]), "+f"((c)[3]) \
                 : "r"((a)[0]), "r"((a)[1]), "r"((a)[2]), "r"((a)[3]), \
                   "r"((b)[0]), "r"((b)[1]))

__device__ __forceinline__ uint32_t pack_bf2(float a, float b) {
    return (uint32_t)__bfloat16_as_ushort(__float2bfloat16(a)) |
           ((uint32_t)__bfloat16_as_ushort(__float2bfloat16(b)) << 16);
}

// ---- K0: word embedding gather -> bf16 hi/lo + pad zero + h init + barrier reset ----
__global__ void k_embed(const int* __restrict__ word_ids,
                        const float* __restrict__ word_emb) {
    int i = blockIdx.x * blockDim.x + threadIdx.x;
    if (i < 8) { g_barc8[i] = 0u; g_barp8[i] = 0u; }
    if (i < BT_ * 75) {
        int n = i / 75, uq = i % 75;
        float4 w = *(const float4*)&word_emb[(long)word_ids[n] * DW_ + uq * 4];
        float h0 = __bfloat162float(__float2bfloat16(w.x));
        float h1 = __bfloat162float(__float2bfloat16(w.y));
        float h2 = __bfloat162float(__float2bfloat16(w.z));
        float h3 = __bfloat162float(__float2bfloat16(w.w));
        uint2 hp, lp;
        hp.x = pack_bf2(w.x, w.y); hp.y = pack_bf2(w.z, w.w);
        lp.x = pack_bf2(w.x - h0, w.y - h1); lp.y = pack_bf2(w.z - h2, w.w - h3);
        long ofs = (long)n * KP_ + uq * 4;
        *(uint2*)&g_Ahi[ofs] = hp;
        *(uint2*)&g_Alo[ofs] = lp;
    }
    if (i < BT_ * 3) {              // zero K-pad cols 500..511
        int n = i / 3, j = i % 3;
        long ofs = (long)n * KP_ + 500 + j * 4;
        *(uint2*)&g_Ahi[ofs] = make_uint2(0u, 0u);
        *(uint2*)&g_Alo[ofs] = make_uint2(0u, 0u);
    }
    if (i < (2 * 2 * B_ * KR_) / 2) {
        ((uint32_t*)g_hhi)[i] = 0u;
        ((uint32_t*)g_hlo)[i] = 0u;
    }
}

// ---- K1: permute word bias to jp order ----
__global__ void k_permB(const float* __restrict__ bf, const float* __restrict__ bb) {
    int i = blockIdx.x * blockDim.x + threadIdx.x;
    if (i >= 2 * GW_) return;
    int d = i / GW_, jp = i % GW_;
    const float* bs = d ? bb : bf;
    g_bwp[d][jp] = bs[(jp & 3) * H_ + (jp >> 2)];
}

// ---- K1b: bf16 hi/lo of word W x-rows (K-major, pad 512) ----
__global__ void k_W2bf(const float* __restrict__ Wf, const float* __restrict__ Wb) {
    int i = blockIdx.x * blockDim.x + threadIdx.x;
    if (i >= 2 * GW_ * KP_) return;
    int d  = i / (GW_ * KP_);
    int jp = (i / KP_) % GW_;
    int k  = i % KP_;
    float v = 0.f;
    if (k < EMB_) {
        const float* W = d ? Wb : Wf;
        v = W[(long)k * GW_ + (jp & 3) * H_ + (jp >> 2)];
    }
    __nv_bfloat16 hi = __float2bfloat16(v);
    __nv_bfloat16 lo = __float2bfloat16(v - __bfloat162float(hi));
    g_Bhi[d][(long)jp * KP_ + k] = hi;
    g_Blo[d][(long)jp * KP_ + k] = lo;
}

// ---- K1c: bf16 hi/lo of word W recurrent rows (K-major, pad 304) ----
__global__ void k_Wr2bf(const float* __restrict__ Wf, const float* __restrict__ Wb) {
    int i = blockIdx.x * blockDim.x + threadIdx.x;
    if (i >= 2 * GW_ * KR_) return;
    int d  = i / (GW_ * KR_);
    int jp = (i / KR_) % GW_;
    int k  = i % KR_;
    float v = 0.f;
    if (k < H_) {
        const float* W = d ? Wb : Wf;
        v = W[(long)(EMB_ + k) * GW_ + (jp & 3) * H_ + (jp >> 2)];
    }
    __nv_bfloat16 hi = __float2bfloat16(v);
    __nv_bfloat16 lo = __float2bfloat16(v - __bfloat162float(hi));
    g_Wrhi[d][(long)jp * KR_ + k] = hi;
    g_Wrlo[d][(long)jp * KR_ + k] = lo;
}

// ---- K1d: bf16 hi/lo of char recurrent W (row jp gate-permuted, K-major pad 112) ----
__global__ void k_Wc2bf(const float* __restrict__ Wf, const float* __restrict__ Wb) {
    int i = blockIdx.x * blockDim.x + threadIdx.x;
    if (i >= 2 * GC_ * CKS) return;
    int d  = i / (GC_ * CKS);
    int jp = (i / CKS) % GC_;
    int k  = i % CKS;
    float v = 0.f;
    if (k < HC_) {
        const float* W = d ? Wb : Wf;
        v = W[(DC_ + k) * GC_ + (jp & 3) * HC_ + (jp >> 2)];
    }
    __nv_bfloat16 hi = __float2bfloat16(v);
    __nv_bfloat16 lo = __float2bfloat16(v - __bfloat162float(hi));
    g_Wchi[d][jp * CKS + k] = hi;
    g_Wclo[d][jp * CKS + k] = lo;
}

// ---- K2: char vocab x-projection ----
__global__ void k_zcv(const float* __restrict__ char_emb,
                      const float* __restrict__ Wf, const float* __restrict__ bf,
                      const float* __restrict__ Wb, const float* __restrict__ bb) {
    int v = blockIdx.x, d = blockIdx.y, jp = threadIdx.x;
    const float* W  = d ? Wb : Wf;
    const float* bs = d ? bb : bf;
    int col = (jp & 3) * HC_ + (jp >> 2);
    float acc = bs[col];
    for (int k = 0; k < DC_; k++)
        acc += char_emb[v * DC_ + k] * W[k * GC_ + col];
    g_zcv[d][v * GC_ + jp] = acc;
}

// ---- K3: char BiLSTM on tensor cores. 64 seqs/block, 640 thr = 20 warps (4M x 5N). ----
#define CB_BHI 0
#define CB_BLO 96000
#define CB_AHI 192000
#define CB_ALO (CB_AHI + 64 * CKSTR * 2)
#define C_SMEM (CB_ALO + 64 * CKSTR * 2)      // 222720

__global__ __launch_bounds__(640, 1)
void k_char(const int* __restrict__ char_ids,
            const int* __restrict__ word_len) {
    int dir  = blockIdx.y;
    int seq0 = blockIdx.x * 64;
    extern __shared__ char smc[];
    __shared__ int slen[64];
    __shared__ int scid[L_][64];
    uint32_t sb = smem_u32(smc);
    int tid = threadIdx.x, wid = tid >> 5, lane = tid & 31;
    int wm = wid & 3, wn = wid >> 2;         // 4 M-warps x 5 N-warps

    const __nv_bfloat16* Bh = g_Wchi[dir];
    const __nv_bfloat16* Bl = g_Wclo[dir];
    for (int i = tid; i < 5600; i += 640) {
        int rr = i / 14, j = i % 14;
        uint32_t d = (uint32_t)(rr * CKSTR + j * 8) * 2;
        *(uint4*)(smc + CB_BHI + d) = *(const uint4*)(Bh + rr * CKS + j * 8);
        *(uint4*)(smc + CB_BLO + d) = *(const uint4*)(Bl + rr * CKS + j * 8);
    }
    for (int i = tid; i < 64 * CKSTR; i += 640)
        ((uint32_t*)(smc + CB_AHI))[i] = 0u;
    if (tid < 64) {
        int len = word_len[seq0 + tid];
        slen[tid] = len;
#pragma unroll
        for (int t = 0; t < L_; t++) {
            int tt = dir ? (len - 1 - t) : t;
            if (tt < 0) tt = 0;
            if (tt >= L_) tt = L_ - 1;
            scid[t][tid] = char_ids[(seq0 + tid) * L_ + tt];
        }
    }

    int myRow = wm * 16 + (lane >> 2) + (lane & 1) * 8;   // 0..63
    int uB    = wn * 20 + ((lane & 3) >> 1);
    bool odd  = (lane & 1) != 0;
    int mi = lane >> 3, rr8 = lane & 7;
    uint32_t aOff = (uint32_t)((wm * 16 + (mi & 1) * 8 + rr8) * CKSTR + (mi >> 1) * 8) * 2;
    uint32_t bOff = (uint32_t)((wn * 80 + (mi >> 1) * 8 + rr8) * CKSTR + (mi & 1) * 8) * 2;

    float creg[10], hreg[10];
#pragma unroll
    for (int f = 0; f < 10; f++) { creg[f] = 0.f; hreg[f] = 0.f; }
    __syncthreads();
    int mylen = slen[myRow];

    for (int t = 0; t < L_; t++) {
        int cid = scid[t][myRow];
        float acc[10][4];
#pragma unroll
        for (int f = 0; f < 10; f++) {
            acc[f][0] = 0.f; acc[f][1] = 0.f; acc[f][2] = 0.f; acc[f][3] = 0.f;
        }
#pragma unroll
        for (int k7 = 0; k7 < 7; k7++) {
            uint32_t ka = (uint32_t)k7 * 32;
            uint32_t ah[4], al[4];
            LDSM_X4(ah[0], ah[1], ah[2], ah[3], sb + CB_AHI + aOff + ka);
            LDSM_X4(al[0], al[1], al[2], al[3], sb + CB_ALO + aOff + ka);
#pragma unroll
            for (int fp = 0; fp < 5; fp++) {
                uint32_t bo = bOff + (uint32_t)(fp * 16 * CKSTR) * 2 + ka;
                uint32_t bh[4], bl[4];
                LDSM_X4(bh[0], bh[1], bh[2], bh[3], sb + CB_BHI + bo);
                LDSM_X4(bl[0], bl[1], bl[2], bl[3], sb + CB_BLO + bo);
                MMA16816(acc[2 * fp],     ah, bh);
                MMA16816(acc[2 * fp],     al, bh);
                MMA16816(acc[2 * fp],     ah, bl);
                MMA16816(acc[2 * fp + 1], ah, bh + 2);
                MMA16816(acc[2 * fp + 1], al, bh + 2);
                MMA16816(acc[2 * fp + 1], ah, bl + 2);
            }
        }
        __syncthreads();

#pragma unroll
        for (int f = 0; f < 10; f++) {
            float4 zxv = __ldg((const float4*)&g_zcv[dir][cid * GC_ + (uB + f * 2) * 4]);
            float e0 = __shfl_xor_sync(0xFFFFFFFFu, acc[f][0], 1);
            float e1 = __shfl_xor_sync(0xFFFFFFFFu, acc[f][1], 1);
            float e2 = __shfl_xor_sync(0xFFFFFFFFu, acc[f][2], 1);
            float e3 = __shfl_xor_sync(0xFFFFFFFFu, acc[f][3], 1);
            float gi = odd ? e2 : acc[f][0];
            float gj = odd ? e3 : acc[f][1];
            float gf = odd ? acc[f][2] : e0;
            float go = odd ? acc[f][3] : e1;
            gi += zxv.x; gj += zxv.y; gf += zxv.z; go += zxv.w;
            float c2 = creg[f] * sigf(gf + 1.f) + sigf(gi) * tanhfast(gj);
            float h2 = sigf(go) * tanhfast(c2);
            if (t < mylen) { creg[f] = c2; hreg[f] = h2; }
            int u = uB + f * 2;
            __nv_bfloat16 hi = __float2bfloat16(hreg[f]);
            __nv_bfloat16 lo = __float2bfloat16(hreg[f] - __bfloat162float(hi));
            *(__nv_bfloat16*)(smc + CB_AHI + (myRow * CKSTR + u) * 2) = hi;
            *(__nv_bfloat16*)(smc + CB_ALO + (myRow * CKSTR + u) * 2) = lo;
        }
        __syncthreads();
    }
    long nb = (long)(seq0 + myRow) * KP_ + DW_ + dir * HC_;
#pragma unroll
    for (int f = 0; f < 10; f++) {
        int u = uB + f * 2;
        __nv_bfloat16 hi = __float2bfloat16(hreg[f]);
        __nv_bfloat16 lo = __float2bfloat16(hreg[f] - __bfloat162float(hi));
        g_Ahi[nb + u] = hi;
        g_Alo[nb + u] = lo;
    }
}

// ---- K4: x-projection via mma.sync bf16 hi/lo (3-pass). Block 128M x 80N. ----
#define XSTR 72
#define XOF_AHI 0
#define XOF_ALO 18432
#define XOF_BHI 36864
#define XOF_BLO 48384
#define XOF_BIAS 59904
#define X_SMEM  (XOF_BIAS + 320)

__global__ __launch_bounds__(256, 2)
void k_xmma() {
    extern __shared__ char smc[];
    int dir = blockIdx.z;
    int m0  = blockIdx.x * 128;
    int c0  = blockIdx.y * 80;
    int tid = threadIdx.x;
    int wid = tid >> 5, lane = tid & 31;
    int wm = wid & 3, wn = wid >> 2;
    float* sbias = (float*)(smc + XOF_BIAS);

    for (int i = tid; i < 80; i += 256) sbias[i] = g_bwp[dir][c0 + i];

    uint32_t sb = smem_u32(smc);
    int r  = lane & 7, mi = lane >> 3;
    int aRow = wm * 32 + (mi & 1) * 8 + r;
    int aCol = (mi >> 1) * 8;
    int bRow = wn * 40 + r;
    int bCol = (mi & 1) * 8;
    uint32_t aOff = (uint32_t)(aRow * XSTR + aCol) * 2;
    uint32_t bOff = (uint32_t)(bRow * XSTR + bCol) * 2;

    float acc[2][5][4];
#pragma unroll
    for (int fm = 0; fm < 2; fm++)
#pragma unroll
        for (int fn = 0; fn < 5; fn++) {
            acc[fm][fn][0] = 0.f; acc[fm][fn][1] = 0.f;
            acc[fm][fn][2] = 0.f; acc[fm][fn][3] = 0.f;
        }

    const __nv_bfloat16* gBh = g_Bhi[dir];
    const __nv_bfloat16* gBl = g_Blo[dir];

    for (int ch = 0; ch < 8; ch++) {
        int kc = ch * 64;
        __syncthreads();
        for (int i = tid; i < 1024; i += 256) {
            int rr = i >> 3, j = i & 7;
            long g = (long)(m0 + rr) * KP_ + kc + j * 8;
            uint32_t d = (uint32_t)(rr * XSTR + j * 8) * 2;
            *(uint4*)(smc + XOF_AHI + d) = *(const uint4*)(g_Ahi + g);
            *(uint4*)(smc + XOF_ALO + d) = *(const uint4*)(g_Alo + g);
        }
        for (int i = tid; i < 640; i += 256) {
            int rr = i >> 3, j = i & 7;
            long g = (long)(c0 + rr) * KP_ + kc + j * 8;
            uint32_t d = (uint32_t)(rr * XSTR + j * 8) * 2;
            *(uint4*)(smc + XOF_BHI + d) = *(const uint4*)(gBh + g);
            *(uint4*)(smc + XOF_BLO + d) = *(const uint4*)(gBl + g);
        }
        __syncthreads();
#pragma unroll
        for (int kk = 0; kk < 64; kk += 16) {
            uint32_t ah[2][4], al[2][4], bh[5][2], bl[5][2];
#pragma unroll
            for (int fm = 0; fm < 2; fm++) {
                uint32_t o = aOff + (uint32_t)(fm * 16 * XSTR + kk) * 2;
                LDSM_X4(ah[fm][0], ah[fm][1], ah[fm][2], ah[fm][3], sb + XOF_AHI + o);
                LDSM_X4(al[fm][0], al[fm][1], al[fm][2], al[fm][3], sb + XOF_ALO + o);
            }
#pragma unroll
            for (int fn = 0; fn < 5; fn++) {
                uint32_t o = bOff + (uint32_t)(fn * 8 * XSTR + kk) * 2;
                LDSM_X2(bh[fn][0], bh[fn][1], sb + XOF_BHI + o);
                LDSM_X2(bl[fn][0], bl[fn][1], sb + XOF_BLO + o);
            }
#pragma unroll
            for (int fm = 0; fm < 2; fm++)
#pragma unroll
                for (int fn = 0; fn < 5; fn++) {
                    MMA16816(acc[fm][fn], ah[fm], bh[fn]);
                    MMA16816(acc[fm][fn], al[fm], bh[fn]);
                    MMA16816(acc[fm][fn], ah[fm], bl[fn]);
                }
        }
    }

    int em = m0 + wm * 32 + (lane >> 2);
    int en = wn * 40 + (lane & 3) * 2;
#pragma unroll
    for (int fm = 0; fm < 2; fm++)
#pragma unroll
        for (int fn = 0; fn < 5; fn++) {
            int mg = em + fm * 16;
            int cg = en + fn * 8;
            float b0 = sbias[cg], b1 = sbias[cg + 1];
            float2 v0, v1;
            v0.x = acc[fm][fn][0] + b0; v0.y = acc[fm][fn][1] + b1;
            v1.x = acc[fm][fn][2] + b0; v1.y = acc[fm][fn][3] + b1;
            *(float2*)&g_zx[dir][(long)mg * GW_ + c0 + cg] = v0;
            *(float2*)&g_zx[dir][(long)(mg + 8) * GW_ + c0 + cg] = v1;
        }
}

// ---- K5: persistent word LSTM on tensor cores. 120 blocks x 320 thr (2M x 5N).
//      Gate gather via lane-pair shuffle (no z smem exchange, one sync/step). ----
#define KSTR 312
#define WS_AHI 0
#define WS_ALO 19968
#define WS_BHI 39936
#define WS_BLO 89856
#define W_SMEM 139776

__global__ __launch_bounds__(320, 1)
void k_wstep(const int* __restrict__ seqlen) {
    int u0c = blockIdx.x * 80;      // jp base
    int u0u = blockIdx.x * 20;      // unit base
    int b0  = blockIdx.y * 32;
    int dir = blockIdx.z;
    int grp = blockIdx.y * 2 + blockIdx.z;
    extern __shared__ char smc[];
    uint32_t sb = smem_u32(smc);
    int tid = threadIdx.x;
    int wid = tid >> 5, lane = tid & 31;
    int wm = wid & 1, wn = wid >> 1;         // 2 M-warps x 5 N-warps

    for (int i = tid; i < 3040; i += 320) {
        int rr = i / 38, j = i % 38;
        uint32_t d = (uint32_t)(rr * KSTR + j * 8) * 2;
        *(uint4*)(smc + WS_BHI + d) = *(const uint4*)(g_Wrhi[dir] + (long)(u0c + rr) * KR_ + j * 8);
        *(uint4*)(smc + WS_BLO + d) = *(const uint4*)(g_Wrlo[dir] + (long)(u0c + rr) * KR_ + j * 8);
    }

    // fragment-aligned cell ownership (same pairing as k_char, verified):
    int myRow = wm * 16 + (lane >> 2) + (lane & 1) * 8;   // batch row 0..31
    bool odd  = (lane & 1) != 0;
    int ua    = (lane & 3) >> 1;
    int uu[2];                       // local units for fn=0,1
    uu[0] = wn * 4 + ua;
    uu[1] = wn * 4 + 2 + ua;
    int len = __ldg(&seqlen[b0 + myRow]);
    float creg[2] = {0.f, 0.f};
    float hreg[2] = {0.f, 0.f};

    int r = lane & 7, mi = lane >> 3;
    uint32_t aOff = (uint32_t)((wm * 16 + (mi & 1) * 8 + r) * KSTR + (mi >> 1) * 8) * 2;
    uint32_t bOff = (uint32_t)((wn * 16 + r) * KSTR + (mi & 1) * 8) * 2;

    unsigned phase = 0;
    for (int t = 0; t < T_; t++) {
        int p = t & 1;
        // prefetch zx for both cells (one gmem row per thread)
        int tt = dir ? ((t < len) ? (len - 1 - t) : t) : t;
        long nrow = (long)((b0 + myRow) * T_ + tt) * GW_;
        float4 zx0 = __ldg((const float4*)&g_zx[dir][nrow + u0c + uu[0] * 4]);
        float4 zx1 = __ldg((const float4*)&g_zx[dir][nrow + u0c + uu[1] * 4]);

        if (t > 0) gbar_grp(grp, phase);
        else __syncthreads();

        const uint4* srcH = (const uint4*)(g_hhi[p][dir] + (long)b0 * KR_);
        const uint4* srcL = (const uint4*)(g_hlo[p][dir] + (long)b0 * KR_);
        for (int i = tid; i < 1216; i += 320) {
            int rr = i / 38, j = i % 38;
            uint32_t d = (uint32_t)(rr * KSTR + j * 8) * 2;
            *(uint4*)(smc + WS_AHI + d) = __ldcg(srcH + rr * 38 + j);
            *(uint4*)(smc + WS_ALO + d) = __ldcg(srcL + rr * 38 + j);
        }
        __syncthreads();

        float acc[2][4];
#pragma unroll
        for (int fn = 0; fn < 2; fn++) {
            acc[fn][0] = 0.f; acc[fn][1] = 0.f; acc[fn][2] = 0.f; acc[fn][3] = 0.f;
        }
#pragma unroll 1
        for (int k16 = 0; k16 < 19; k16++) {
            uint32_t kk2 = (uint32_t)(k16 * 16) * 2;
            uint32_t ah[4], al[4];
            LDSM_X4(ah[0], ah[1], ah[2], ah[3], sb + WS_AHI + aOff + kk2);
            LDSM_X4(al[0], al[1], al[2], al[3], sb + WS_ALO + aOff + kk2);
#pragma unroll
            for (int fn = 0; fn < 2; fn++) {
                uint32_t o = bOff + (uint32_t)(fn * 8 * KSTR) * 2 + kk2;
                uint32_t bh[2], bl[2];
                LDSM_X2(bh[0], bh[1], sb + WS_BHI + o);
                LDSM_X2(bl[0], bl[1], sb + WS_BLO + o);
                MMA16816(acc[fn], ah, bh);
                MMA16816(acc[fn], al, bh);
                MMA16816(acc[fn], ah, bl);
            }
        }

        // gate gather via lane-pair shuffle, update state, publish h hi/lo
#pragma unroll
        for (int fn = 0; fn < 2; fn++) {
            float e0 = __shfl_xor_sync(0xFFFFFFFFu, acc[fn][0], 1);
            float e1 = __shfl_xor_sync(0xFFFFFFFFu, acc[fn][1], 1);
            float e2 = __shfl_xor_sync(0xFFFFFFFFu, acc[fn][2], 1);
            float e3 = __shfl_xor_sync(0xFFFFFFFFu, acc[fn][3], 1);
            float gi = odd ? e2 : acc[fn][0];
            float gj = odd ? e3 : acc[fn][1];
            float gf = odd ? acc[fn][2] : e0;
            float go = odd ? acc[fn][3] : e1;
            float4 zx = fn ? zx1 : zx0;
            gi += zx.x; gj += zx.y; gf += zx.z; go += zx.w;
            float cnew = creg[fn] * sigf(gf + 1.f) + sigf(gi) * tanhfast(gj);
            float hnew = sigf(go) * tanhfast(cnew);
            if (t >= len) { cnew = creg[fn]; hnew = hreg[fn]; }
            creg[fn] = cnew; hreg[fn] = hnew;
            __nv_bfloat16 hi = __float2bfloat16(hnew);
            __nv_bfloat16 lo = __float2bfloat16(hnew - __bfloat162float(hi));
            long idx = (long)(b0 + myRow) * KR_ + u0u + uu[fn];
            g_hhi[p ^ 1][dir][idx] = hi;
            g_hlo[p ^ 1][dir][idx] = lo;
        }
    }
#pragma unroll
    for (int fn = 0; fn < 2; fn++)
        g_c[dir][(b0 + myRow) * H_ + u0u + uu[fn]] = creg[fn];
}

// ---- K6: projection + log_softmax + NLL mean ----
__global__ void k_final(const int* __restrict__ labels,
                        const float* __restrict__ Wp,
                        const float* __restrict__ bp,
                        float* __restrict__ out) {
    __shared__ float red[128];
    int b = threadIdx.x;
    float l0 = bp[0], l1 = bp[1], l2 = bp[2];
    for (int k = 0; k < H_; k++) {
        float v = g_c[0][b * H_ + k];
        l0 += v * Wp[k * 3 + 0]; l1 += v * Wp[k * 3 + 1]; l2 += v * Wp[k * 3 + 2];
    }
    for (int k = 0; k < H_; k++) {
        float v = g_c[1][b * H_ + k];
        l0 += v * Wp[(H_ + k) * 3 + 0]; l1 += v * Wp[(H_ + k) * 3 + 1]; l2 += v * Wp[(H_ + k) * 3 + 2];
    }
    float m = fmaxf(l0, fmaxf(l1, l2));
    float lse = m + logf(expf(l0 - m) + expf(l1 - m) + expf(l2 - m));
    int lab = labels[b];
    float lp = ((lab == 0) ? l0 : (lab == 1) ? l1 : l2) - lse;
    red[b] = lp;
    __syncthreads();
    for (int s = 64; s > 0; s >>= 1) {
        if (b < s) red[b] += red[b + s];
        __syncthreads();
    }
    if (b == 0) out[0] = -red[0] / 128.f;
}

extern "C" void kernel_launch(void* const* d_in, const int* in_sizes, int n_in,
                              void* d_out, int out_size) {
    (void)in_sizes; (void)n_in; (void)out_size;
    const int*   word_ids = (const int*)  d_in[0];
    const int*   seq_len  = (const int*)  d_in[1];
    const int*   char_ids = (const int*)  d_in[2];
    const int*   word_len = (const int*)  d_in[3];
    const int*   labels   = (const int*)  d_in[4];
    const float* word_emb = (const float*)d_in[5];
    const float* char_emb = (const float*)d_in[6];
    const float* Wc_fw    = (const float*)d_in[7];
    const float* bc_fw    = (const float*)d_in[8];
    const float* Wc_bw    = (const float*)d_in[9];
    const float* bc_bw    = (const float*)d_in[10];
    const float* Ww_fw    = (const float*)d_in[11];
    const float* bw_fw    = (const float*)d_in[12];
    const float* Ww_bw    = (const float*)d_in[13];
    const float* bw_bw    = (const float*)d_in[14];
    const float* W_proj   = (const float*)d_in[15];
    const float* b_proj   = (const float*)d_in[16];
    float* out = (float*)d_out;

    cudaFuncSetAttribute(k_char, cudaFuncAttributeMaxDynamicSharedMemorySize, C_SMEM);
    cudaFuncSetAttribute(k_xmma, cudaFuncAttributeMaxDynamicSharedMemorySize, X_SMEM);
    cudaFuncSetAttribute(k_wstep, cudaFuncAttributeMaxDynamicSharedMemorySize, W_SMEM);

    // order: k_char is the 4th launch (the one ncu captures)
    k_embed<<<(BT_ * 75 + 255) / 256, 256>>>(word_ids, word_emb);
    k_Wc2bf<<<(2 * GC_ * CKS + 255) / 256, 256>>>(Wc_fw, Wc_bw);
    k_zcv<<<dim3(NV_, 2), GC_>>>(char_emb, Wc_fw, bc_fw, Wc_bw, bc_bw);
    k_char<<<dim3(BT_ / 64, 2), 640, C_SMEM>>>(char_ids, word_len);
    k_permB<<<(2 * GW_ + 255) / 256, 256>>>(bw_fw, bw_bw);
    k_W2bf<<<(2 * GW_ * KP_ + 255) / 256, 256>>>(Ww_fw, Ww_bw);
    k_Wr2bf<<<(2 * GW_ * KR_ + 255) / 256, 256>>>(Ww_fw, Ww_bw);
    k_xmma<<<dim3(BT_ / 128, 15, 2), 256, X_SMEM>>>();
    k_wstep<<<dim3(15, 4, 2), 320, W_SMEM>>>(seq_len);
    k_final<<<1, 128>>>(labels, W_proj, b_proj, out);
}

// round 16
// speedup vs baseline: 1.1066x; 1.1066x over previous
#include <cuda_runtime.h>
#include <cuda_bf16.h>
#include <cstdint>
#include <math.h>

#define B_   128
#define T_   256
#define L_   16
#define DW_  300
#define DC_  100
#define HC_  100
#define H_   300
#define NT_  3
#define NV_  101          // char vocab rows (NC+1)
#define EMB_ 500          // DW + 2*HC
#define KP_  512          // padded K for x-proj MMA
#define KR_  304          // padded K for recurrent word MMA
#define CKS  112          // padded K for char recurrent MMA (100 -> 7x16)
#define CKSTR 120         // smem row stride (bf16) for char MMA tiles
#define GW_  1200         // 4*H
#define GC_  400          // 4*HC
#define BT_  32768        // B*T
#define GRP_BLK 15        // u-tile blocks per (b,dir) barrier group

// ---------------- static device scratch (no runtime allocation) ----------------
__device__ __align__(16) float g_zx[2][BT_ * GW_];       // x-projection (gate-permuted)
__device__ __align__(16) float g_bwp[2][GW_];            // permuted word bias
__device__ __align__(16) float g_zcv[2][NV_ * GC_];      // char vocab x-proj
__device__ __align__(16) float g_c[2][B_ * H_];          // word cell state (output)
// bf16 hi/lo activations for the x-proj MMA: word emb (k_embed) + char rep (k_char)
__device__ __align__(16) __nv_bfloat16 g_Ahi[BT_ * KP_];
__device__ __align__(16) __nv_bfloat16 g_Alo[BT_ * KP_];
__device__ __align__(16) __nv_bfloat16 g_Bhi[2][GW_ * KP_];
__device__ __align__(16) __nv_bfloat16 g_Blo[2][GW_ * KP_];
// bf16 hi/lo of recurrent word W, row jp, K-major padded to 304
__device__ __align__(16) __nv_bfloat16 g_Wrhi[2][GW_ * KR_];
__device__ __align__(16) __nv_bfloat16 g_Wrlo[2][GW_ * KR_];
// bf16 hi/lo of char recurrent W, row jp (gate-permuted), K-major padded to 112
__device__ __align__(16) __nv_bfloat16 g_Wchi[2][GC_ * CKS];
__device__ __align__(16) __nv_bfloat16 g_Wclo[2][GC_ * CKS];
// word h as bf16 hi/lo (double-buffered by parity): [parity][dir][B*304]
__device__ __align__(16) __nv_bfloat16 g_hhi[2][2][B_ * KR_];
__device__ __align__(16) __nv_bfloat16 g_hlo[2][2][B_ * KR_];
// per-group grid barrier state (8 groups of 15 blocks)
__device__ volatile unsigned g_barc8[8];
__device__ volatile unsigned g_barp8[8];

__device__ __forceinline__ float sigf(float x) {
    return __fdividef(1.f, 1.f + __expf(-x));
}
__device__ __forceinline__ float tanhfast(float x) {
    x = fminf(fmaxf(x, -15.f), 15.f);
    float e = __expf(2.f * x);
    return __fdividef(e - 1.f, e + 1.f);
}

__device__ __forceinline__ void gbar_grp(int g, unsigned& phase) {
    __threadfence();
    __syncthreads();
    if (threadIdx.x == 0) {
        unsigned old = atomicAdd((unsigned*)&g_barc8[g], 1u);
        if (old == GRP_BLK - 1u) {
            g_barc8[g] = 0u;
            __threadfence();
            atomicAdd((unsigned*)&g_barp8[g], 1u);
        } else {
            while (g_barp8[g] <= phase) { }
        }
    }
    __syncthreads();
    phase++;
}

// ---------------- warp-level MMA helpers ----------------
__device__ __forceinline__ uint32_t smem_u32(const void* p) {
    uint32_t a;
    asm("{ .reg .u64 t; cvta.to.shared.u64 t, %1; cvt.u32.u64 %0, t; }" : "=r"(a) : "l"(p));
    return a;
}
#define LDSM_X4(r0, r1, r2, r3, addr) \
    asm volatile("ldmatrix.sync.aligned.m8n8.x4.shared.b16 {%0,%1,%2,%3}, [%4];" \
                 : "=r"(r0), "=r"(r1), "=r"(r2), "=r"(r3) : "r"(addr))
#define LDSM_X2(r0, r1, addr) \
    asm volatile("ldmatrix.sync.aligned.m8n8.x2.shared.b16 {%0,%1}, [%2];" \
                 : "=r"(r0), "=r"(r1) : "r"(addr))
#define MMA16816(c, a, b) \
    asm volatile("mma.sync.aligned.m16n8k16.row.col.f32.bf16.bf16.f32 " \
                 "{%0,%1,%2,%3}, {%4,%5,%6,%7}, {%8,%9}, {%0,%1,%2,%3};" \
                 : "+f"((c)[0]), "+f"((c)[1]), "+f"((c)[2]), "+f"((c)[3]) \
                 : "r"((a)[0]), "r"((a)[1]), "r"((a)[2]), "r"((a)[3]), \
                   "r"((b)[0]), "r"((b)[1]))
#define CP_ASYNC16(smaddr, gptr) \
    asm volatile("cp.async.cg.shared.global [%0], [%1], 16;" :: "r"(smaddr), "l"(gptr))
#define CP_COMMIT() asm volatile("cp.async.commit_group;" ::: "memory")
#define CP_WAIT0()  asm volatile("cp.async.wait_group 0;" ::: "memory")

__device__ __forceinline__ uint32_t pack_bf2(float a, float b) {
    return (uint32_t)__bfloat16_as_ushort(__float2bfloat16(a)) |
           ((uint32_t)__bfloat16_as_ushort(__float2bfloat16(b)) << 16);
}

// ---- K0: word embedding gather -> bf16 hi/lo + pad zero + h init + barrier reset ----
__global__ void k_embed(const int* __restrict__ word_ids,
                        const float* __restrict__ word_emb) {
    int i = blockIdx.x * blockDim.x + threadIdx.x;
    if (i < 8) { g_barc8[i] = 0u; g_barp8[i] = 0u; }
    if (i < BT_ * 75) {
        int n = i / 75, uq = i % 75;
        float4 w = *(const float4*)&word_emb[(long)word_ids[n] * DW_ + uq * 4];
        float h0 = __bfloat162float(__float2bfloat16(w.x));
        float h1 = __bfloat162float(__float2bfloat16(w.y));
        float h2 = __bfloat162float(__float2bfloat16(w.z));
        float h3 = __bfloat162float(__float2bfloat16(w.w));
        uint2 hp, lp;
        hp.x = pack_bf2(w.x, w.y); hp.y = pack_bf2(w.z, w.w);
        lp.x = pack_bf2(w.x - h0, w.y - h1); lp.y = pack_bf2(w.z - h2, w.w - h3);
        long ofs = (long)n * KP_ + uq * 4;
        *(uint2*)&g_Ahi[ofs] = hp;
        *(uint2*)&g_Alo[ofs] = lp;
    }
    if (i < BT_ * 3) {              // zero K-pad cols 500..511
        int n = i / 3, j = i % 3;
        long ofs = (long)n * KP_ + 500 + j * 4;
        *(uint2*)&g_Ahi[ofs] = make_uint2(0u, 0u);
        *(uint2*)&g_Alo[ofs] = make_uint2(0u, 0u);
    }
    if (i < (2 * 2 * B_ * KR_) / 2) {
        ((uint32_t*)g_hhi)[i] = 0u;
        ((uint32_t*)g_hlo)[i] = 0u;
    }
}

// ---- K1: permute word bias to jp order ----
__global__ void k_permB(const float* __restrict__ bf, const float* __restrict__ bb) {
    int i = blockIdx.x * blockDim.x + threadIdx.x;
    if (i >= 2 * GW_) return;
    int d = i / GW_, jp = i % GW_;
    const float* bs = d ? bb : bf;
    g_bwp[d][jp] = bs[(jp & 3) * H_ + (jp >> 2)];
}

// ---- K1b: bf16 hi/lo of word W x-rows (K-major, pad 512) ----
__global__ void k_W2bf(const float* __restrict__ Wf, const float* __restrict__ Wb) {
    int i = blockIdx.x * blockDim.x + threadIdx.x;
    if (i >= 2 * GW_ * KP_) return;
    int d  = i / (GW_ * KP_);
    int jp = (i / KP_) % GW_;
    int k  = i % KP_;
    float v = 0.f;
    if (k < EMB_) {
        const float* W = d ? Wb : Wf;
        v = W[(long)k * GW_ + (jp & 3) * H_ + (jp >> 2)];
    }
    __nv_bfloat16 hi = __float2bfloat16(v);
    __nv_bfloat16 lo = __float2bfloat16(v - __bfloat162float(hi));
    g_Bhi[d][(long)jp * KP_ + k] = hi;
    g_Blo[d][(long)jp * KP_ + k] = lo;
}

// ---- K1c: bf16 hi/lo of word W recurrent rows (K-major, pad 304) ----
__global__ void k_Wr2bf(const float* __restrict__ Wf, const float* __restrict__ Wb) {
    int i = blockIdx.x * blockDim.x + threadIdx.x;
    if (i >= 2 * GW_ * KR_) return;
    int d  = i / (GW_ * KR_);
    int jp = (i / KR_) % GW_;
    int k  = i % KR_;
    float v = 0.f;
    if (k < H_) {
        const float* W = d ? Wb : Wf;
        v = W[(long)(EMB_ + k) * GW_ + (jp & 3) * H_ + (jp >> 2)];
    }
    __nv_bfloat16 hi = __float2bfloat16(v);
    __nv_bfloat16 lo = __float2bfloat16(v - __bfloat162float(hi));
    g_Wrhi[d][(long)jp * KR_ + k] = hi;
    g_Wrlo[d][(long)jp * KR_ + k] = lo;
}

// ---- K1d: bf16 hi/lo of char recurrent W (row jp gate-permuted, K-major pad 112) ----
__global__ void k_Wc2bf(const float* __restrict__ Wf, const float* __restrict__ Wb) {
    int i = blockIdx.x * blockDim.x + threadIdx.x;
    if (i >= 2 * GC_ * CKS) return;
    int d  = i / (GC_ * CKS);
    int jp = (i / CKS) % GC_;
    int k  = i % CKS;
    float v = 0.f;
    if (k < HC_) {
        const float* W = d ? Wb : Wf;
        v = W[(DC_ + k) * GC_ + (jp & 3) * HC_ + (jp >> 2)];
    }
    __nv_bfloat16 hi = __float2bfloat16(v);
    __nv_bfloat16 lo = __float2bfloat16(v - __bfloat162float(hi));
    g_Wchi[d][jp * CKS + k] = hi;
    g_Wclo[d][jp * CKS + k] = lo;
}

// ---- K2: char vocab x-projection ----
__global__ void k_zcv(const float* __restrict__ char_emb,
                      const float* __restrict__ Wf, const float* __restrict__ bf,
                      const float* __restrict__ Wb, const float* __restrict__ bb) {
    int v = blockIdx.x, d = blockIdx.y, jp = threadIdx.x;
    const float* W  = d ? Wb : Wf;
    const float* bs = d ? bb : bf;
    int col = (jp & 3) * HC_ + (jp >> 2);
    float acc = bs[col];
    for (int k = 0; k < DC_; k++)
        acc += char_emb[v * DC_ + k] * W[k * GC_ + col];
    g_zcv[d][v * GC_ + jp] = acc;
}

// ---- K3: char BiLSTM on tensor cores. 64 seqs/block, 640 thr = 20 warps (4M x 5N). ----
#define CB_BHI 0
#define CB_BLO 96000
#define CB_AHI 192000
#define CB_ALO (CB_AHI + 64 * CKSTR * 2)
#define C_SMEM (CB_ALO + 64 * CKSTR * 2)      // 222720

__global__ __launch_bounds__(640, 1)
void k_char(const int* __restrict__ char_ids,
            const int* __restrict__ word_len) {
    int dir  = blockIdx.y;
    int seq0 = blockIdx.x * 64;
    extern __shared__ char smc[];
    __shared__ int slen[64];
    __shared__ int scid[L_][64];
    uint32_t sb = smem_u32(smc);
    int tid = threadIdx.x, wid = tid >> 5, lane = tid & 31;
    int wm = wid & 3, wn = wid >> 2;         // 4 M-warps x 5 N-warps

    const __nv_bfloat16* Bh = g_Wchi[dir];
    const __nv_bfloat16* Bl = g_Wclo[dir];
    for (int i = tid; i < 5600; i += 640) {
        int rr = i / 14, j = i % 14;
        uint32_t d = (uint32_t)(rr * CKSTR + j * 8) * 2;
        *(uint4*)(smc + CB_BHI + d) = *(const uint4*)(Bh + rr * CKS + j * 8);
        *(uint4*)(smc + CB_BLO + d) = *(const uint4*)(Bl + rr * CKS + j * 8);
    }
    for (int i = tid; i < 64 * CKSTR; i += 640)
        ((uint32_t*)(smc + CB_AHI))[i] = 0u;
    if (tid < 64) {
        int len = word_len[seq0 + tid];
        slen[tid] = len;
#pragma unroll
        for (int t = 0; t < L_; t++) {
            int tt = dir ? (len - 1 - t) : t;
            if (tt < 0) tt = 0;
            if (tt >= L_) tt = L_ - 1;
            scid[t][tid] = char_ids[(seq0 + tid) * L_ + tt];
        }
    }

    int myRow = wm * 16 + (lane >> 2) + (lane & 1) * 8;   // 0..63
    int uB    = wn * 20 + ((lane & 3) >> 1);
    bool odd  = (lane & 1) != 0;
    int mi = lane >> 3, rr8 = lane & 7;
    uint32_t aOff = (uint32_t)((wm * 16 + (mi & 1) * 8 + rr8) * CKSTR + (mi >> 1) * 8) * 2;
    uint32_t bOff = (uint32_t)((wn * 80 + (mi >> 1) * 8 + rr8) * CKSTR + (mi & 1) * 8) * 2;

    float creg[10], hreg[10];
#pragma unroll
    for (int f = 0; f < 10; f++) { creg[f] = 0.f; hreg[f] = 0.f; }
    __syncthreads();
    int mylen = slen[myRow];

    for (int t = 0; t < L_; t++) {
        int cid = scid[t][myRow];
        float acc[10][4];
#pragma unroll
        for (int f = 0; f < 10; f++) {
            acc[f][0] = 0.f; acc[f][1] = 0.f; acc[f][2] = 0.f; acc[f][3] = 0.f;
        }
#pragma unroll
        for (int k7 = 0; k7 < 7; k7++) {
            uint32_t ka = (uint32_t)k7 * 32;
            uint32_t ah[4], al[4];
            LDSM_X4(ah[0], ah[1], ah[2], ah[3], sb + CB_AHI + aOff + ka);
            LDSM_X4(al[0], al[1], al[2], al[3], sb + CB_ALO + aOff + ka);
#pragma unroll
            for (int fp = 0; fp < 5; fp++) {
                uint32_t bo = bOff + (uint32_t)(fp * 16 * CKSTR) * 2 + ka;
                uint32_t bh[4], bl[4];
                LDSM_X4(bh[0], bh[1], bh[2], bh[3], sb + CB_BHI + bo);
                LDSM_X4(bl[0], bl[1], bl[2], bl[3], sb + CB_BLO + bo);
                MMA16816(acc[2 * fp],     ah, bh);
                MMA16816(acc[2 * fp],     al, bh);
                MMA16816(acc[2 * fp],     ah, bl);
                MMA16816(acc[2 * fp + 1], ah, bh + 2);
                MMA16816(acc[2 * fp + 1], al, bh + 2);
                MMA16816(acc[2 * fp + 1], ah, bl + 2);
            }
        }
        __syncthreads();

#pragma unroll
        for (int f = 0; f < 10; f++) {
            float4 zxv = __ldg((const float4*)&g_zcv[dir][cid * GC_ + (uB + f * 2) * 4]);
            float e0 = __shfl_xor_sync(0xFFFFFFFFu, acc[f][0], 1);
            float e1 = __shfl_xor_sync(0xFFFFFFFFu, acc[f][1], 1);
            float e2 = __shfl_xor_sync(0xFFFFFFFFu, acc[f][2], 1);
            float e3 = __shfl_xor_sync(0xFFFFFFFFu, acc[f][3], 1);
            float gi = odd ? e2 : acc[f][0];
            float gj = odd ? e3 : acc[f][1];
            float gf = odd ? acc[f][2] : e0;
            float go = odd ? acc[f][3] : e1;
            gi += zxv.x; gj += zxv.y; gf += zxv.z; go += zxv.w;
            float c2 = creg[f] * sigf(gf + 1.f) + sigf(gi) * tanhfast(gj);
            float h2 = sigf(go) * tanhfast(c2);
            if (t < mylen) { creg[f] = c2; hreg[f] = h2; }
            int u = uB + f * 2;
            __nv_bfloat16 hi = __float2bfloat16(hreg[f]);
            __nv_bfloat16 lo = __float2bfloat16(hreg[f] - __bfloat162float(hi));
            *(__nv_bfloat16*)(smc + CB_AHI + (myRow * CKSTR + u) * 2) = hi;
            *(__nv_bfloat16*)(smc + CB_ALO + (myRow * CKSTR + u) * 2) = lo;
        }
        __syncthreads();
    }
    long nb = (long)(seq0 + myRow) * KP_ + DW_ + dir * HC_;
#pragma unroll
    for (int f = 0; f < 10; f++) {
        int u = uB + f * 2;
        __nv_bfloat16 hi = __float2bfloat16(hreg[f]);
        __nv_bfloat16 lo = __float2bfloat16(hreg[f] - __bfloat162float(hi));
        g_Ahi[nb + u] = hi;
        g_Alo[nb + u] = lo;
    }
}

// ---- K4: x-projection, cp.async double-buffered. Block 128M x 120N, 384 thr (4M x 3N). ----
#define XSTR 72
#define XB_AHI 0
#define XB_ALO 18432
#define XB_BHI 36864
#define XB_BLO 54144
#define XPB    71424            // bytes per stage buffer
#define XB_BIAS (2 * XPB)       // 142848
#define X_SMEM  (XB_BIAS + 480) // 143328

__global__ __launch_bounds__(384, 1)
void k_xmma() {
    extern __shared__ char smc[];
    int dir = blockIdx.z;
    int m0  = blockIdx.x * 128;
    int c0  = blockIdx.y * 120;
    int tid = threadIdx.x;
    int wid = tid >> 5, lane = tid & 31;
    int wm = wid & 3, wn = wid >> 2;         // 4 M-warps x 3 N-warps (40 cols each)
    float* sbias = (float*)(smc + XB_BIAS);
    uint32_t sb = smem_u32(smc);

    for (int i = tid; i < 120; i += 384) sbias[i] = g_bwp[dir][c0 + i];

    const __nv_bfloat16* gBh = g_Bhi[dir];
    const __nv_bfloat16* gBl = g_Blo[dir];

    // stage chunk `ch` into buffer `s` via cp.async (16B each)
    auto stage = [&](int ch, int s) {
        int kc = ch * 64;
        uint32_t bb = sb + s * XPB;
        for (int i = tid; i < 1024; i += 384) {
            int rr = i >> 3, j = i & 7;
            long g = (long)(m0 + rr) * KP_ + kc + j * 8;
            uint32_t d = (uint32_t)(rr * XSTR + j * 8) * 2;
            CP_ASYNC16(bb + XB_AHI + d, g_Ahi + g);
            CP_ASYNC16(bb + XB_ALO + d, g_Alo + g);
        }
        for (int i = tid; i < 960; i += 384) {
            int rr = i >> 3, j = i & 7;
            long g = (long)(c0 + rr) * KP_ + kc + j * 8;
            uint32_t d = (uint32_t)(rr * XSTR + j * 8) * 2;
            CP_ASYNC16(bb + XB_BHI + d, gBh + g);
            CP_ASYNC16(bb + XB_BLO + d, gBl + g);
        }
        CP_COMMIT();
    };

    int r  = lane & 7, mi = lane >> 3;
    uint32_t aOff = (uint32_t)((wm * 32 + (mi & 1) * 8 + r) * XSTR + (mi >> 1) * 8) * 2;
    uint32_t bOff = (uint32_t)((wn * 40 + r) * XSTR + (mi & 1) * 8) * 2;

    float acc[2][5][4];
#pragma unroll
    for (int fm = 0; fm < 2; fm++)
#pragma unroll
        for (int fn = 0; fn < 5; fn++) {
            acc[fm][fn][0] = 0.f; acc[fm][fn][1] = 0.f;
            acc[fm][fn][2] = 0.f; acc[fm][fn][3] = 0.f;
        }

    stage(0, 0);
    for (int ch = 0; ch < 8; ch++) {
        CP_WAIT0();
        __syncthreads();                 // data for ch visible; compute(ch-1) done
        if (ch < 7) stage(ch + 1, (ch + 1) & 1);
        uint32_t bb = sb + (ch & 1) * XPB;
#pragma unroll
        for (int kk = 0; kk < 64; kk += 16) {
            uint32_t ah[2][4], al[2][4], bh[5][2], bl[5][2];
#pragma unroll
            for (int fm = 0; fm < 2; fm++) {
                uint32_t o = aOff + (uint32_t)(fm * 16 * XSTR + kk) * 2;
                LDSM_X4(ah[fm][0], ah[fm][1], ah[fm][2], ah[fm][3], bb + XB_AHI + o);
                LDSM_X4(al[fm][0], al[fm][1], al[fm][2], al[fm][3], bb + XB_ALO + o);
            }
#pragma unroll
            for (int fn = 0; fn < 5; fn++) {
                uint32_t o = bOff + (uint32_t)(fn * 8 * XSTR + kk) * 2;
                LDSM_X2(bh[fn][0], bh[fn][1], bb + XB_BHI + o);
                LDSM_X2(bl[fn][0], bl[fn][1], bb + XB_BLO + o);
            }
#pragma unroll
            for (int fm = 0; fm < 2; fm++)
#pragma unroll
                for (int fn = 0; fn < 5; fn++) {
                    MMA16816(acc[fm][fn], ah[fm], bh[fn]);
                    MMA16816(acc[fm][fn], al[fm], bh[fn]);
                    MMA16816(acc[fm][fn], ah[fm], bl[fn]);
                }
        }
    }

    int em = m0 + wm * 32 + (lane >> 2);
    int en = wn * 40 + (lane & 3) * 2;
#pragma unroll
    for (int fm = 0; fm < 2; fm++)
#pragma unroll
        for (int fn = 0; fn < 5; fn++) {
            int mg = em + fm * 16;
            int cg = en + fn * 8;
            float b0 = sbias[cg], b1 = sbias[cg + 1];
            float2 v0, v1;
            v0.x = acc[fm][fn][0] + b0; v0.y = acc[fm][fn][1] + b1;
            v1.x = acc[fm][fn][2] + b0; v1.y = acc[fm][fn][3] + b1;
            *(float2*)&g_zx[dir][(long)mg * GW_ + c0 + cg] = v0;
            *(float2*)&g_zx[dir][(long)(mg + 8) * GW_ + c0 + cg] = v1;
        }
}

// ---- K5: persistent word LSTM on tensor cores. 120 blocks x 320 thr (2M x 5N). ----
#define KSTR 312
#define WS_AHI 0
#define WS_ALO 19968
#define WS_BHI 39936
#define WS_BLO 89856
#define WS_Z   139776
#define W_SMEM 150016

__global__ __launch_bounds__(320, 1)
void k_wstep(const int* __restrict__ seqlen) {
    int u0c = blockIdx.x * 80;
    int u0u = blockIdx.x * 20;
    int b0  = blockIdx.y * 32;
    int dir = blockIdx.z;
    int grp = blockIdx.y * 2 + blockIdx.z;
    extern __shared__ char smc[];
    float* zsm = (float*)(smc + WS_Z);
    uint32_t sb = smem_u32(smc);
    int tid = threadIdx.x;
    int wid = tid >> 5, lane = tid & 31;
    int wm = wid & 1, wn = wid >> 1;

    for (int i = tid; i < 3040; i += 320) {
        int rr = i / 38, j = i % 38;
        uint32_t d = (uint32_t)(rr * KSTR + j * 8) * 2;
        *(uint4*)(smc + WS_BHI + d) = *(const uint4*)(g_Wrhi[dir] + (long)(u0c + rr) * KR_ + j * 8);
        *(uint4*)(smc + WS_BLO + d) = *(const uint4*)(g_Wrlo[dir] + (long)(u0c + rr) * KR_ + j * 8);
    }

    int cb[2], cul[2], clen[2];
#pragma unroll
    for (int cc = 0; cc < 2; cc++) {
        int cell = tid + cc * 320;
        cb[cc]  = cell / 20;
        cul[cc] = cell % 20;
        clen[cc] = __ldg(&seqlen[b0 + cb[cc]]);
    }
    float creg[2] = {0.f, 0.f};
    float hreg[2] = {0.f, 0.f};

    int r = lane & 7, mi = lane >> 3;
    uint32_t aOff = (uint32_t)((wm * 16 + (mi & 1) * 8 + r) * KSTR + (mi >> 1) * 8) * 2;
    uint32_t bOff = (uint32_t)((wn * 16 + r) * KSTR + (mi & 1) * 8) * 2;
    int em = wm * 16 + (lane >> 2);
    int en = wn * 16 + (lane & 3) * 2;

    unsigned phase = 0;
    for (int t = 0; t < T_; t++) {
        int p = t & 1;
        float4 zx[2];
#pragma unroll
        for (int cc = 0; cc < 2; cc++) {
            int len = clen[cc];
            int tt = dir ? ((t < len) ? (len - 1 - t) : t) : t;
            zx[cc] = __ldg((const float4*)&g_zx[dir][(long)((b0 + cb[cc]) * T_ + tt) * GW_ + u0c + cul[cc] * 4]);
        }
        if (t > 0) gbar_grp(grp, phase);
        else __syncthreads();

        const uint4* srcH = (const uint4*)(g_hhi[p][dir] + (long)b0 * KR_);
        const uint4* srcL = (const uint4*)(g_hlo[p][dir] + (long)b0 * KR_);
        for (int i = tid; i < 1216; i += 320) {
            int rr = i / 38, j = i % 38;
            uint32_t d = (uint32_t)(rr * KSTR + j * 8) * 2;
            *(uint4*)(smc + WS_AHI + d) = __ldcg(srcH + rr * 38 + j);
            *(uint4*)(smc + WS_ALO + d) = __ldcg(srcL + rr * 38 + j);
        }
        __syncthreads();

        float acc[2][4];
#pragma unroll
        for (int fn = 0; fn < 2; fn++) {
            acc[fn][0] = 0.f; acc[fn][1] = 0.f; acc[fn][2] = 0.f; acc[fn][3] = 0.f;
        }
#pragma unroll 1
        for (int k16 = 0; k16 < 19; k16++) {
            uint32_t kk2 = (uint32_t)(k16 * 16) * 2;
            uint32_t ah[4], al[4];
            LDSM_X4(ah[0], ah[1], ah[2], ah[3], sb + WS_AHI + aOff + kk2);
            LDSM_X4(al[0], al[1], al[2], al[3], sb + WS_ALO + aOff + kk2);
#pragma unroll
            for (int fn = 0; fn < 2; fn++) {
                uint32_t o = bOff + (uint32_t)(fn * 8 * KSTR) * 2 + kk2;
                uint32_t bh[2], bl[2];
                LDSM_X2(bh[0], bh[1], sb + WS_BHI + o);
                LDSM_X2(bl[0], bl[1], sb + WS_BLO + o);
                MMA16816(acc[fn], ah, bh);
                MMA16816(acc[fn], al, bh);
                MMA16816(acc[fn], ah, bl);
            }
        }
#pragma unroll
        for (int fn = 0; fn < 2; fn++) {
            *(float2*)&zsm[em * 80 + en + fn * 8]       = make_float2(acc[fn][0], acc[fn][1]);
            *(float2*)&zsm[(em + 8) * 80 + en + fn * 8] = make_float2(acc[fn][2], acc[fn][3]);
        }
        __syncthreads();

#pragma unroll
        for (int cc = 0; cc < 2; cc++) {
            float4 z4 = *(const float4*)&zsm[cb[cc] * 80 + cul[cc] * 4];
            float iv = zx[cc].x + z4.x, jv = zx[cc].y + z4.y;
            float fv = zx[cc].z + z4.z, ov = zx[cc].w + z4.w;
            float cnew = creg[cc] * sigf(fv + 1.f) + sigf(iv) * tanhfast(jv);
            float hnew = sigf(ov) * tanhfast(cnew);
            if (t >= clen[cc]) { cnew = creg[cc]; hnew = hreg[cc]; }
            creg[cc] = cnew; hreg[cc] = hnew;
            __nv_bfloat16 hi = __float2bfloat16(hnew);
            __nv_bfloat16 lo = __float2bfloat16(hnew - __bfloat162float(hi));
            long idx = (long)(b0 + cb[cc]) * KR_ + u0u + cul[cc];
            g_hhi[p ^ 1][dir][idx] = hi;
            g_hlo[p ^ 1][dir][idx] = lo;
        }
    }
#pragma unroll
    for (int cc = 0; cc < 2; cc++)
        g_c[dir][(b0 + cb[cc]) * H_ + u0u + cul[cc]] = creg[cc];
}

// ---- K6: projection + log_softmax + NLL mean ----
__global__ void k_final(const int* __restrict__ labels,
                        const float* __restrict__ Wp,
                        const float* __restrict__ bp,
                        float* __restrict__ out) {
    __shared__ float red[128];
    int b = threadIdx.x;
    float l0 = bp[0], l1 = bp[1], l2 = bp[2];
    for (int k = 0; k < H_; k++) {
        float v = g_c[0][b * H_ + k];
        l0 += v * Wp[k * 3 + 0]; l1 += v * Wp[k * 3 + 1]; l2 += v * Wp[k * 3 + 2];
    }
    for (int k = 0; k < H_; k++) {
        float v = g_c[1][b * H_ + k];
        l0 += v * Wp[(H_ + k) * 3 + 0]; l1 += v * Wp[(H_ + k) * 3 + 1]; l2 += v * Wp[(H_ + k) * 3 + 2];
    }
    float m = fmaxf(l0, fmaxf(l1, l2));
    float lse = m + logf(expf(l0 - m) + expf(l1 - m) + expf(l2 - m));
    int lab = labels[b];
    float lp = ((lab == 0) ? l0 : (lab == 1) ? l1 : l2) - lse;
    red[b] = lp;
    __syncthreads();
    for (int s = 64; s > 0; s >>= 1) {
        if (b < s) red[b] += red[b + s];
        __syncthreads();
    }
    if (b == 0) out[0] = -red[0] / 128.f;
}

extern "C" void kernel_launch(void* const* d_in, const int* in_sizes, int n_in,
                              void* d_out, int out_size) {
    (void)in_sizes; (void)n_in; (void)out_size;
    const int*   word_ids = (const int*)  d_in[0];
    const int*   seq_len  = (const int*)  d_in[1];
    const int*   char_ids = (const int*)  d_in[2];
    const int*   word_len = (const int*)  d_in[3];
    const int*   labels   = (const int*)  d_in[4];
    const float* word_emb = (const float*)d_in[5];
    const float* char_emb = (const float*)d_in[6];
    const float* Wc_fw    = (const float*)d_in[7];
    const float* bc_fw    = (const float*)d_in[8];
    const float* Wc_bw    = (const float*)d_in[9];
    const float* bc_bw    = (const float*)d_in[10];
    const float* Ww_fw    = (const float*)d_in[11];
    const float* bw_fw    = (const float*)d_in[12];
    const float* Ww_bw    = (const float*)d_in[13];
    const float* bw_bw    = (const float*)d_in[14];
    const float* W_proj   = (const float*)d_in[15];
    const float* b_proj   = (const float*)d_in[16];
    float* out = (float*)d_out;

    cudaFuncSetAttribute(k_char, cudaFuncAttributeMaxDynamicSharedMemorySize, C_SMEM);
    cudaFuncSetAttribute(k_xmma, cudaFuncAttributeMaxDynamicSharedMemorySize, X_SMEM);
    cudaFuncSetAttribute(k_wstep, cudaFuncAttributeMaxDynamicSharedMemorySize, W_SMEM);

    // order: k_char is the 4th launch (the one ncu captures)
    k_embed<<<(BT_ * 75 + 255) / 256, 256>>>(word_ids, word_emb);
    k_Wc2bf<<<(2 * GC_ * CKS + 255) / 256, 256>>>(Wc_fw, Wc_bw);
    k_zcv<<<dim3(NV_, 2), GC_>>>(char_emb, Wc_fw, bc_fw, Wc_bw, bc_bw);
    k_char<<<dim3(BT_ / 64, 2), 640, C_SMEM>>>(char_ids, word_len);
    k_permB<<<(2 * GW_ + 255) / 256, 256>>>(bw_fw, bw_bw);
    k_W2bf<<<(2 * GW_ * KP_ + 255) / 256, 256>>>(Ww_fw, Ww_bw);
    k_Wr2bf<<<(2 * GW_ * KR_ + 255) / 256, 256>>>(Ww_fw, Ww_bw);
    k_xmma<<<dim3(BT_ / 128, 10, 2), 384, X_SMEM>>>();
    k_wstep<<<dim3(15, 4, 2), 320, W_SMEM>>>(seq_len);
    k_final<<<1, 128>>>(labels, W_proj, b_proj, out);
}

// round 17
// speedup vs baseline: 1.1345x; 1.0252x over previous
#include <cuda_runtime.h>
#include <cuda_bf16.h>
#include <cstdint>
#include <math.h>

#define B_   128
#define T_   256
#define L_   16
#define DW_  300
#define DC_  100
#define HC_  100
#define H_   300
#define NT_  3
#define NV_  101          // char vocab rows (NC+1)
#define EMB_ 500          // DW + 2*HC
#define KP_  512          // padded K for x-proj MMA
#define KR_  304          // padded K for recurrent word MMA
#define CKS  112          // padded K for char recurrent MMA (100 -> 7x16)
#define CKSTR 120         // smem row stride (bf16) for char MMA tiles
#define GW_  1200         // 4*H
#define GC_  400          // 4*HC
#define BT_  32768        // B*T
#define GRP_BLK 15        // u-tile blocks per (b,dir) barrier group

// ---------------- static device scratch (no runtime allocation) ----------------
__device__ __align__(16) float g_zx[2][BT_ * GW_];       // x-projection (gate-permuted)
__device__ __align__(16) float g_bwp[2][GW_];            // permuted word bias
__device__ __align__(16) float g_zcv[2][NV_ * GC_];      // char vocab x-proj
__device__ __align__(16) float g_c[2][B_ * H_];          // word cell state (output)
// bf16 hi/lo activations for the x-proj MMA: word emb (k_embed) + char rep (k_char)
__device__ __align__(16) __nv_bfloat16 g_Ahi[BT_ * KP_];
__device__ __align__(16) __nv_bfloat16 g_Alo[BT_ * KP_];
__device__ __align__(16) __nv_bfloat16 g_Bhi[2][GW_ * KP_];
__device__ __align__(16) __nv_bfloat16 g_Blo[2][GW_ * KP_];
// bf16 hi/lo of recurrent word W, row jp, K-major padded to 304
__device__ __align__(16) __nv_bfloat16 g_Wrhi[2][GW_ * KR_];
__device__ __align__(16) __nv_bfloat16 g_Wrlo[2][GW_ * KR_];
// bf16 hi/lo of char recurrent W, row jp (gate-permuted), K-major padded to 112
__device__ __align__(16) __nv_bfloat16 g_Wchi[2][GC_ * CKS];
__device__ __align__(16) __nv_bfloat16 g_Wclo[2][GC_ * CKS];
// word h as bf16 hi/lo (double-buffered by parity), indexed by SORTED SLOT
__device__ __align__(16) __nv_bfloat16 g_hhi[2][2][B_ * KR_];
__device__ __align__(16) __nv_bfloat16 g_hlo[2][2][B_ * KR_];
// length-sorted batch permutation + per-btile max length
__device__ int g_perm[B_];
__device__ int g_tmax[4];
// per-group grid barrier state (8 groups of 15 blocks)
__device__ volatile unsigned g_barc8[8];
__device__ volatile unsigned g_barp8[8];

__device__ __forceinline__ float sigf(float x) {
    return __fdividef(1.f, 1.f + __expf(-x));
}
__device__ __forceinline__ float tanhfast(float x) {
    x = fminf(fmaxf(x, -15.f), 15.f);
    float e = __expf(2.f * x);
    return __fdividef(e - 1.f, e + 1.f);
}

__device__ __forceinline__ void gbar_grp(int g, unsigned& phase) {
    __threadfence();
    __syncthreads();
    if (threadIdx.x == 0) {
        unsigned old = atomicAdd((unsigned*)&g_barc8[g], 1u);
        if (old == GRP_BLK - 1u) {
            g_barc8[g] = 0u;
            __threadfence();
            atomicAdd((unsigned*)&g_barp8[g], 1u);
        } else {
            while (g_barp8[g] <= phase) { }
        }
    }
    __syncthreads();
    phase++;
}

// ---------------- warp-level MMA helpers ----------------
__device__ __forceinline__ uint32_t smem_u32(const void* p) {
    uint32_t a;
    asm("{ .reg .u64 t; cvta.to.shared.u64 t, %1; cvt.u32.u64 %0, t; }" : "=r"(a) : "l"(p));
    return a;
}
#define LDSM_X4(r0, r1, r2, r3, addr) \
    asm volatile("ldmatrix.sync.aligned.m8n8.x4.shared.b16 {%0,%1,%2,%3}, [%4];" \
                 : "=r"(r0), "=r"(r1), "=r"(r2), "=r"(r3) : "r"(addr))
#define LDSM_X2(r0, r1, addr) \
    asm volatile("ldmatrix.sync.aligned.m8n8.x2.shared.b16 {%0,%1}, [%2];" \
                 : "=r"(r0), "=r"(r1) : "r"(addr))
#define MMA16816(c, a, b) \
    asm volatile("mma.sync.aligned.m16n8k16.row.col.f32.bf16.bf16.f32 " \
                 "{%0,%1,%2,%3}, {%4,%5,%6,%7}, {%8,%9}, {%0,%1,%2,%3};" \
                 : "+f"((c)[0]), "+f"((c)[1]), "+f"((c)[2]), "+f"((c)[3]) \
                 : "r"((a)[0]), "r"((a)[1]), "r"((a)[2]), "r"((a)[3]), \
                   "r"((b)[0]), "r"((b)[1]))
#define CP_ASYNC16(smaddr, gptr) \
    asm volatile("cp.async.cg.shared.global [%0], [%1], 16;" :: "r"(smaddr), "l"(gptr))
#define CP_COMMIT() asm volatile("cp.async.commit_group;" ::: "memory")
#define CP_WAIT0()  asm volatile("cp.async.wait_group 0;" ::: "memory")

__device__ __forceinline__ uint32_t pack_bf2(float a, float b) {
    return (uint32_t)__bfloat16_as_ushort(__float2bfloat16(a)) |
           ((uint32_t)__bfloat16_as_ushort(__float2bfloat16(b)) << 16);
}

// ---- K0: word embedding gather -> bf16 hi/lo + pad zero + h init + barrier reset ----
__global__ void k_embed(const int* __restrict__ word_ids,
                        const float* __restrict__ word_emb) {
    int i = blockIdx.x * blockDim.x + threadIdx.x;
    if (i < 8) { g_barc8[i] = 0u; g_barp8[i] = 0u; }
    if (i < BT_ * 75) {
        int n = i / 75, uq = i % 75;
        float4 w = *(const float4*)&word_emb[(long)word_ids[n] * DW_ + uq * 4];
        float h0 = __bfloat162float(__float2bfloat16(w.x));
        float h1 = __bfloat162float(__float2bfloat16(w.y));
        float h2 = __bfloat162float(__float2bfloat16(w.z));
        float h3 = __bfloat162float(__float2bfloat16(w.w));
        uint2 hp, lp;
        hp.x = pack_bf2(w.x, w.y); hp.y = pack_bf2(w.z, w.w);
        lp.x = pack_bf2(w.x - h0, w.y - h1); lp.y = pack_bf2(w.z - h2, w.w - h3);
        long ofs = (long)n * KP_ + uq * 4;
        *(uint2*)&g_Ahi[ofs] = hp;
        *(uint2*)&g_Alo[ofs] = lp;
    }
    if (i < BT_ * 3) {              // zero K-pad cols 500..511
        int n = i / 3, j = i % 3;
        long ofs = (long)n * KP_ + 500 + j * 4;
        *(uint2*)&g_Ahi[ofs] = make_uint2(0u, 0u);
        *(uint2*)&g_Alo[ofs] = make_uint2(0u, 0u);
    }
    if (i < (2 * 2 * B_ * KR_) / 2) {
        ((uint32_t*)g_hhi)[i] = 0u;
        ((uint32_t*)g_hlo)[i] = 0u;
    }
}

// ---- K0b: rank-sort batch rows by length (ascending); per-btile Tmax ----
__global__ void k_sort(const int* __restrict__ seqlen) {
    __shared__ int lens[B_];
    __shared__ int smax[4];
    int i = threadIdx.x;
    lens[i] = seqlen[i];
    if (i < 4) smax[i] = 0;
    __syncthreads();
    int li = lens[i];
    int rank = 0;
    for (int j = 0; j < B_; j++) {
        int lj = lens[j];
        rank += (lj < li) || (lj == li && j < i);
    }
    g_perm[rank] = i;
    atomicMax(&smax[rank >> 5], li);
    __syncthreads();
    if (i < 4) g_tmax[i] = smax[i];
}

// ---- K1: permute word bias to jp order ----
__global__ void k_permB(const float* __restrict__ bf, const float* __restrict__ bb) {
    int i = blockIdx.x * blockDim.x + threadIdx.x;
    if (i >= 2 * GW_) return;
    int d = i / GW_, jp = i % GW_;
    const float* bs = d ? bb : bf;
    g_bwp[d][jp] = bs[(jp & 3) * H_ + (jp >> 2)];
}

// ---- K1b: bf16 hi/lo of word W x-rows (K-major, pad 512) ----
__global__ void k_W2bf(const float* __restrict__ Wf, const float* __restrict__ Wb) {
    int i = blockIdx.x * blockDim.x + threadIdx.x;
    if (i >= 2 * GW_ * KP_) return;
    int d  = i / (GW_ * KP_);
    int jp = (i / KP_) % GW_;
    int k  = i % KP_;
    float v = 0.f;
    if (k < EMB_) {
        const float* W = d ? Wb : Wf;
        v = W[(long)k * GW_ + (jp & 3) * H_ + (jp >> 2)];
    }
    __nv_bfloat16 hi = __float2bfloat16(v);
    __nv_bfloat16 lo = __float2bfloat16(v - __bfloat162float(hi));
    g_Bhi[d][(long)jp * KP_ + k] = hi;
    g_Blo[d][(long)jp * KP_ + k] = lo;
}

// ---- K1c: bf16 hi/lo of word W recurrent rows (K-major, pad 304) ----
__global__ void k_Wr2bf(const float* __restrict__ Wf, const float* __restrict__ Wb) {
    int i = blockIdx.x * blockDim.x + threadIdx.x;
    if (i >= 2 * GW_ * KR_) return;
    int d  = i / (GW_ * KR_);
    int jp = (i / KR_) % GW_;
    int k  = i % KR_;
    float v = 0.f;
    if (k < H_) {
        const float* W = d ? Wb : Wf;
        v = W[(long)(EMB_ + k) * GW_ + (jp & 3) * H_ + (jp >> 2)];
    }
    __nv_bfloat16 hi = __float2bfloat16(v);
    __nv_bfloat16 lo = __float2bfloat16(v - __bfloat162float(hi));
    g_Wrhi[d][(long)jp * KR_ + k] = hi;
    g_Wrlo[d][(long)jp * KR_ + k] = lo;
}

// ---- K1d: bf16 hi/lo of char recurrent W (row jp gate-permuted, K-major pad 112) ----
__global__ void k_Wc2bf(const float* __restrict__ Wf, const float* __restrict__ Wb) {
    int i = blockIdx.x * blockDim.x + threadIdx.x;
    if (i >= 2 * GC_ * CKS) return;
    int d  = i / (GC_ * CKS);
    int jp = (i / CKS) % GC_;
    int k  = i % CKS;
    float v = 0.f;
    if (k < HC_) {
        const float* W = d ? Wb : Wf;
        v = W[(DC_ + k) * GC_ + (jp & 3) * HC_ + (jp >> 2)];
    }
    __nv_bfloat16 hi = __float2bfloat16(v);
    __nv_bfloat16 lo = __float2bfloat16(v - __bfloat162float(hi));
    g_Wchi[d][jp * CKS + k] = hi;
    g_Wclo[d][jp * CKS + k] = lo;
}

// ---- K2: char vocab x-projection ----
__global__ void k_zcv(const float* __restrict__ char_emb,
                      const float* __restrict__ Wf, const float* __restrict__ bf,
                      const float* __restrict__ Wb, const float* __restrict__ bb) {
    int v = blockIdx.x, d = blockIdx.y, jp = threadIdx.x;
    const float* W  = d ? Wb : Wf;
    const float* bs = d ? bb : bf;
    int col = (jp & 3) * HC_ + (jp >> 2);
    float acc = bs[col];
    for (int k = 0; k < DC_; k++)
        acc += char_emb[v * DC_ + k] * W[k * GC_ + col];
    g_zcv[d][v * GC_ + jp] = acc;
}

// ---- K3: char BiLSTM on tensor cores. 64 seqs/block, 640 thr = 20 warps (4M x 5N). ----
#define CB_BHI 0
#define CB_BLO 96000
#define CB_AHI 192000
#define CB_ALO (CB_AHI + 64 * CKSTR * 2)
#define C_SMEM (CB_ALO + 64 * CKSTR * 2)      // 222720

__global__ __launch_bounds__(640, 1)
void k_char(const int* __restrict__ char_ids,
            const int* __restrict__ word_len) {
    int dir  = blockIdx.y;
    int seq0 = blockIdx.x * 64;
    extern __shared__ char smc[];
    __shared__ int slen[64];
    __shared__ int scid[L_][64];
    uint32_t sb = smem_u32(smc);
    int tid = threadIdx.x, wid = tid >> 5, lane = tid & 31;
    int wm = wid & 3, wn = wid >> 2;         // 4 M-warps x 5 N-warps

    const __nv_bfloat16* Bh = g_Wchi[dir];
    const __nv_bfloat16* Bl = g_Wclo[dir];
    for (int i = tid; i < 5600; i += 640) {
        int rr = i / 14, j = i % 14;
        uint32_t d = (uint32_t)(rr * CKSTR + j * 8) * 2;
        *(uint4*)(smc + CB_BHI + d) = *(const uint4*)(Bh + rr * CKS + j * 8);
        *(uint4*)(smc + CB_BLO + d) = *(const uint4*)(Bl + rr * CKS + j * 8);
    }
    for (int i = tid; i < 64 * CKSTR; i += 640)
        ((uint32_t*)(smc + CB_AHI))[i] = 0u;
    if (tid < 64) {
        int len = word_len[seq0 + tid];
        slen[tid] = len;
#pragma unroll
        for (int t = 0; t < L_; t++) {
            int tt = dir ? (len - 1 - t) : t;
            if (tt < 0) tt = 0;
            if (tt >= L_) tt = L_ - 1;
            scid[t][tid] = char_ids[(seq0 + tid) * L_ + tt];
        }
    }

    int myRow = wm * 16 + (lane >> 2) + (lane & 1) * 8;   // 0..63
    int uB    = wn * 20 + ((lane & 3) >> 1);
    bool odd  = (lane & 1) != 0;
    int mi = lane >> 3, rr8 = lane & 7;
    uint32_t aOff = (uint32_t)((wm * 16 + (mi & 1) * 8 + rr8) * CKSTR + (mi >> 1) * 8) * 2;
    uint32_t bOff = (uint32_t)((wn * 80 + (mi >> 1) * 8 + rr8) * CKSTR + (mi & 1) * 8) * 2;

    float creg[10], hreg[10];
#pragma unroll
    for (int f = 0; f < 10; f++) { creg[f] = 0.f; hreg[f] = 0.f; }
    __syncthreads();
    int mylen = slen[myRow];

    for (int t = 0; t < L_; t++) {
        int cid = scid[t][myRow];
        float acc[10][4];
#pragma unroll
        for (int f = 0; f < 10; f++) {
            acc[f][0] = 0.f; acc[f][1] = 0.f; acc[f][2] = 0.f; acc[f][3] = 0.f;
        }
#pragma unroll
        for (int k7 = 0; k7 < 7; k7++) {
            uint32_t ka = (uint32_t)k7 * 32;
            uint32_t ah[4], al[4];
            LDSM_X4(ah[0], ah[1], ah[2], ah[3], sb + CB_AHI + aOff + ka);
            LDSM_X4(al[0], al[1], al[2], al[3], sb + CB_ALO + aOff + ka);
#pragma unroll
            for (int fp = 0; fp < 5; fp++) {
                uint32_t bo = bOff + (uint32_t)(fp * 16 * CKSTR) * 2 + ka;
                uint32_t bh[4], bl[4];
                LDSM_X4(bh[0], bh[1], bh[2], bh[3], sb + CB_BHI + bo);
                LDSM_X4(bl[0], bl[1], bl[2], bl[3], sb + CB_BLO + bo);
                MMA16816(acc[2 * fp],     ah, bh);
                MMA16816(acc[2 * fp],     al, bh);
                MMA16816(acc[2 * fp],     ah, bl);
                MMA16816(acc[2 * fp + 1], ah, bh + 2);
                MMA16816(acc[2 * fp + 1], al, bh + 2);
                MMA16816(acc[2 * fp + 1], ah, bl + 2);
            }
        }
        __syncthreads();

#pragma unroll
        for (int f = 0; f < 10; f++) {
            float4 zxv = __ldg((const float4*)&g_zcv[dir][cid * GC_ + (uB + f * 2) * 4]);
            float e0 = __shfl_xor_sync(0xFFFFFFFFu, acc[f][0], 1);
            float e1 = __shfl_xor_sync(0xFFFFFFFFu, acc[f][1], 1);
            float e2 = __shfl_xor_sync(0xFFFFFFFFu, acc[f][2], 1);
            float e3 = __shfl_xor_sync(0xFFFFFFFFu, acc[f][3], 1);
            float gi = odd ? e2 : acc[f][0];
            float gj = odd ? e3 : acc[f][1];
            float gf = odd ? acc[f][2] : e0;
            float go = odd ? acc[f][3] : e1;
            gi += zxv.x; gj += zxv.y; gf += zxv.z; go += zxv.w;
            float c2 = creg[f] * sigf(gf + 1.f) + sigf(gi) * tanhfast(gj);
            float h2 = sigf(go) * tanhfast(c2);
            if (t < mylen) { creg[f] = c2; hreg[f] = h2; }
            int u = uB + f * 2;
            __nv_bfloat16 hi = __float2bfloat16(hreg[f]);
            __nv_bfloat16 lo = __float2bfloat16(hreg[f] - __bfloat162float(hi));
            *(__nv_bfloat16*)(smc + CB_AHI + (myRow * CKSTR + u) * 2) = hi;
            *(__nv_bfloat16*)(smc + CB_ALO + (myRow * CKSTR + u) * 2) = lo;
        }
        __syncthreads();
    }
    long nb = (long)(seq0 + myRow) * KP_ + DW_ + dir * HC_;
#pragma unroll
    for (int f = 0; f < 10; f++) {
        int u = uB + f * 2;
        __nv_bfloat16 hi = __float2bfloat16(hreg[f]);
        __nv_bfloat16 lo = __float2bfloat16(hreg[f] - __bfloat162float(hi));
        g_Ahi[nb + u] = hi;
        g_Alo[nb + u] = lo;
    }
}

// ---- K4: x-projection, cp.async double-buffered. Block 128M x 120N, 384 thr (4M x 3N). ----
#define XSTR 72
#define XB_AHI 0
#define XB_ALO 18432
#define XB_BHI 36864
#define XB_BLO 54144
#define XPB    71424            // bytes per stage buffer
#define XB_BIAS (2 * XPB)       // 142848
#define X_SMEM  (XB_BIAS + 480) // 143328

__global__ __launch_bounds__(384, 1)
void k_xmma() {
    extern __shared__ char smc[];
    int dir = blockIdx.z;
    int m0  = blockIdx.x * 128;
    int c0  = blockIdx.y * 120;
    int tid = threadIdx.x;
    int wid = tid >> 5, lane = tid & 31;
    int wm = wid & 3, wn = wid >> 2;         // 4 M-warps x 3 N-warps (40 cols each)
    float* sbias = (float*)(smc + XB_BIAS);
    uint32_t sb = smem_u32(smc);

    for (int i = tid; i < 120; i += 384) sbias[i] = g_bwp[dir][c0 + i];

    const __nv_bfloat16* gBh = g_Bhi[dir];
    const __nv_bfloat16* gBl = g_Blo[dir];

    auto stage = [&](int ch, int s) {
        int kc = ch * 64;
        uint32_t bb = sb + s * XPB;
        for (int i = tid; i < 1024; i += 384) {
            int rr = i >> 3, j = i & 7;
            long g = (long)(m0 + rr) * KP_ + kc + j * 8;
            uint32_t d = (uint32_t)(rr * XSTR + j * 8) * 2;
            CP_ASYNC16(bb + XB_AHI + d, g_Ahi + g);
            CP_ASYNC16(bb + XB_ALO + d, g_Alo + g);
        }
        for (int i = tid; i < 960; i += 384) {
            int rr = i >> 3, j = i & 7;
            long g = (long)(c0 + rr) * KP_ + kc + j * 8;
            uint32_t d = (uint32_t)(rr * XSTR + j * 8) * 2;
            CP_ASYNC16(bb + XB_BHI + d, gBh + g);
            CP_ASYNC16(bb + XB_BLO + d, gBl + g);
        }
        CP_COMMIT();
    };

    int r  = lane & 7, mi = lane >> 3;
    uint32_t aOff = (uint32_t)((wm * 32 + (mi & 1) * 8 + r) * XSTR + (mi >> 1) * 8) * 2;
    uint32_t bOff = (uint32_t)((wn * 40 + r) * XSTR + (mi & 1) * 8) * 2;

    float acc[2][5][4];
#pragma unroll
    for (int fm = 0; fm < 2; fm++)
#pragma unroll
        for (int fn = 0; fn < 5; fn++) {
            acc[fm][fn][0] = 0.f; acc[fm][fn][1] = 0.f;
            acc[fm][fn][2] = 0.f; acc[fm][fn][3] = 0.f;
        }

    stage(0, 0);
    for (int ch = 0; ch < 8; ch++) {
        CP_WAIT0();
        __syncthreads();
        if (ch < 7) stage(ch + 1, (ch + 1) & 1);
        uint32_t bb = sb + (ch & 1) * XPB;
#pragma unroll
        for (int kk = 0; kk < 64; kk += 16) {
            uint32_t ah[2][4], al[2][4], bh[5][2], bl[5][2];
#pragma unroll
            for (int fm = 0; fm < 2; fm++) {
                uint32_t o = aOff + (uint32_t)(fm * 16 * XSTR + kk) * 2;
                LDSM_X4(ah[fm][0], ah[fm][1], ah[fm][2], ah[fm][3], bb + XB_AHI + o);
                LDSM_X4(al[fm][0], al[fm][1], al[fm][2], al[fm][3], bb + XB_ALO + o);
            }
#pragma unroll
            for (int fn = 0; fn < 5; fn++) {
                uint32_t o = bOff + (uint32_t)(fn * 8 * XSTR + kk) * 2;
                LDSM_X2(bh[fn][0], bh[fn][1], bb + XB_BHI + o);
                LDSM_X2(bl[fn][0], bl[fn][1], bb + XB_BLO + o);
            }
#pragma unroll
            for (int fm = 0; fm < 2; fm++)
#pragma unroll
                for (int fn = 0; fn < 5; fn++) {
                    MMA16816(acc[fm][fn], ah[fm], bh[fn]);
                    MMA16816(acc[fm][fn], al[fm], bh[fn]);
                    MMA16816(acc[fm][fn], ah[fm], bl[fn]);
                }
        }
    }

    int em = m0 + wm * 32 + (lane >> 2);
    int en = wn * 40 + (lane & 3) * 2;
#pragma unroll
    for (int fm = 0; fm < 2; fm++)
#pragma unroll
        for (int fn = 0; fn < 5; fn++) {
            int mg = em + fm * 16;
            int cg = en + fn * 8;
            float b0 = sbias[cg], b1 = sbias[cg + 1];
            float2 v0, v1;
            v0.x = acc[fm][fn][0] + b0; v0.y = acc[fm][fn][1] + b1;
            v1.x = acc[fm][fn][2] + b0; v1.y = acc[fm][fn][3] + b1;
            *(float2*)&g_zx[dir][(long)mg * GW_ + c0 + cg] = v0;
            *(float2*)&g_zx[dir][(long)(mg + 8) * GW_ + c0 + cg] = v1;
        }
}

// ---- K5: persistent word LSTM on tensor cores. 120 blocks x 320 thr (2M x 5N).
//      Batch rows length-sorted into slots; each group runs its own Tmax steps. ----
#define KSTR 312
#define WS_AHI 0
#define WS_ALO 19968
#define WS_BHI 39936
#define WS_BLO 89856
#define WS_Z   139776
#define W_SMEM 150016

__global__ __launch_bounds__(320, 1)
void k_wstep(const int* __restrict__ seqlen) {
    int u0c = blockIdx.x * 80;
    int u0u = blockIdx.x * 20;
    int b0  = blockIdx.y * 32;       // slot base
    int dir = blockIdx.z;
    int grp = blockIdx.y * 2 + blockIdx.z;
    int tmax = g_tmax[blockIdx.y];
    extern __shared__ char smc[];
    float* zsm = (float*)(smc + WS_Z);
    uint32_t sb = smem_u32(smc);
    int tid = threadIdx.x;
    int wid = tid >> 5, lane = tid & 31;
    int wm = wid & 1, wn = wid >> 1;

    for (int i = tid; i < 3040; i += 320) {
        int rr = i / 38, j = i % 38;
        uint32_t d = (uint32_t)(rr * KSTR + j * 8) * 2;
        *(uint4*)(smc + WS_BHI + d) = *(const uint4*)(g_Wrhi[dir] + (long)(u0c + rr) * KR_ + j * 8);
        *(uint4*)(smc + WS_BLO + d) = *(const uint4*)(g_Wrlo[dir] + (long)(u0c + rr) * KR_ + j * 8);
    }

    int cb[2], cul[2], clen[2], bb[2];
#pragma unroll
    for (int cc = 0; cc < 2; cc++) {
        int cell = tid + cc * 320;
        cb[cc]  = cell / 20;                 // slot within tile 0..31
        cul[cc] = cell % 20;
        bb[cc]  = g_perm[b0 + cb[cc]];       // actual batch row
        clen[cc] = __ldg(&seqlen[bb[cc]]);
    }
    float creg[2] = {0.f, 0.f};
    float hreg[2] = {0.f, 0.f};

    int r = lane & 7, mi = lane >> 3;
    uint32_t aOff = (uint32_t)((wm * 16 + (mi & 1) * 8 + r) * KSTR + (mi >> 1) * 8) * 2;
    uint32_t bOff = (uint32_t)((wn * 16 + r) * KSTR + (mi & 1) * 8) * 2;
    int em = wm * 16 + (lane >> 2);
    int en = wn * 16 + (lane & 3) * 2;

    unsigned phase = 0;
    for (int t = 0; t < tmax; t++) {
        int p = t & 1;
        float4 zx[2];
#pragma unroll
        for (int cc = 0; cc < 2; cc++) {
            int len = clen[cc];
            int tt = dir ? ((t < len) ? (len - 1 - t) : t) : t;
            zx[cc] = __ldg((const float4*)&g_zx[dir][(long)(bb[cc] * T_ + tt) * GW_ + u0c + cul[cc] * 4]);
        }
        if (t > 0) gbar_grp(grp, phase);
        else __syncthreads();

        const uint4* srcH = (const uint4*)(g_hhi[p][dir] + (long)b0 * KR_);
        const uint4* srcL = (const uint4*)(g_hlo[p][dir] + (long)b0 * KR_);
        for (int i = tid; i < 1216; i += 320) {
            int rr = i / 38, j = i % 38;
            uint32_t d = (uint32_t)(rr * KSTR + j * 8) * 2;
            *(uint4*)(smc + WS_AHI + d) = __ldcg(srcH + rr * 38 + j);
            *(uint4*)(smc + WS_ALO + d) = __ldcg(srcL + rr * 38 + j);
        }
        __syncthreads();

        float acc[2][4];
#pragma unroll
        for (int fn = 0; fn < 2; fn++) {
            acc[fn][0] = 0.f; acc[fn][1] = 0.f; acc[fn][2] = 0.f; acc[fn][3] = 0.f;
        }
#pragma unroll 1
        for (int k16 = 0; k16 < 19; k16++) {
            uint32_t kk2 = (uint32_t)(k16 * 16) * 2;
            uint32_t ah[4], al[4];
            LDSM_X4(ah[0], ah[1], ah[2], ah[3], sb + WS_AHI + aOff + kk2);
            LDSM_X4(al[0], al[1], al[2], al[3], sb + WS_ALO + aOff + kk2);
#pragma unroll
            for (int fn = 0; fn < 2; fn++) {
                uint32_t o = bOff + (uint32_t)(fn * 8 * KSTR) * 2 + kk2;
                uint32_t bh[2], bl[2];
                LDSM_X2(bh[0], bh[1], sb + WS_BHI + o);
                LDSM_X2(bl[0], bl[1], sb + WS_BLO + o);
                MMA16816(acc[fn], ah, bh);
                MMA16816(acc[fn], al, bh);
                MMA16816(acc[fn], ah, bl);
            }
        }
#pragma unroll
        for (int fn = 0; fn < 2; fn++) {
            *(float2*)&zsm[em * 80 + en + fn * 8]       = make_float2(acc[fn][0], acc[fn][1]);
            *(float2*)&zsm[(em + 8) * 80 + en + fn * 8] = make_float2(acc[fn][2], acc[fn][3]);
        }
        __syncthreads();

#pragma unroll
        for (int cc = 0; cc < 2; cc++) {
            float4 z4 = *(const float4*)&zsm[cb[cc] * 80 + cul[cc] * 4];
            float iv = zx[cc].x + z4.x, jv = zx[cc].y + z4.y;
            float fv = zx[cc].z + z4.z, ov = zx[cc].w + z4.w;
            float cnew = creg[cc] * sigf(fv + 1.f) + sigf(iv) * tanhfast(jv);
            float hnew = sigf(ov) * tanhfast(cnew);
            if (t >= clen[cc]) { cnew = creg[cc]; hnew = hreg[cc]; }
            creg[cc] = cnew; hreg[cc] = hnew;
            __nv_bfloat16 hi = __float2bfloat16(hnew);
            __nv_bfloat16 lo = __float2bfloat16(hnew - __bfloat162float(hi));
            long idx = (long)(b0 + cb[cc]) * KR_ + u0u + cul[cc];
            g_hhi[p ^ 1][dir][idx] = hi;
            g_hlo[p ^ 1][dir][idx] = lo;
        }
    }
#pragma unroll
    for (int cc = 0; cc < 2; cc++)
        g_c[dir][bb[cc] * H_ + u0u + cul[cc]] = creg[cc];
}

// ---- K6: projection + log_softmax + NLL mean ----
__global__ void k_final(const int* __restrict__ labels,
                        const float* __restrict__ Wp,
                        const float* __restrict__ bp,
                        float* __restrict__ out) {
    __shared__ float red[128];
    int b = threadIdx.x;
    float l0 = bp[0], l1 = bp[1], l2 = bp[2];
    for (int k = 0; k < H_; k++) {
        float v = g_c[0][b * H_ + k];
        l0 += v * Wp[k * 3 + 0]; l1 += v * Wp[k * 3 + 1]; l2 += v * Wp[k * 3 + 2];
    }
    for (int k = 0; k < H_; k++) {
        float v = g_c[1][b * H_ + k];
        l0 += v * Wp[(H_ + k) * 3 + 0]; l1 += v * Wp[(H_ + k) * 3 + 1]; l2 += v * Wp[(H_ + k) * 3 + 2];
    }
    float m = fmaxf(l0, fmaxf(l1, l2));
    float lse = m + logf(expf(l0 - m) + expf(l1 - m) + expf(l2 - m));
    int lab = labels[b];
    float lp = ((lab == 0) ? l0 : (lab == 1) ? l1 : l2) - lse;
    red[b] = lp;
    __syncthreads();
    for (int s = 64; s > 0; s >>= 1) {
        if (b < s) red[b] += red[b + s];
        __syncthreads();
    }
    if (b == 0) out[0] = -red[0] / 128.f;
}

extern "C" void kernel_launch(void* const* d_in, const int* in_sizes, int n_in,
                              void* d_out, int out_size) {
    (void)in_sizes; (void)n_in; (void)out_size;
    const int*   word_ids = (const int*)  d_in[0];
    const int*   seq_len  = (const int*)  d_in[1];
    const int*   char_ids = (const int*)  d_in[2];
    const int*   word_len = (const int*)  d_in[3];
    const int*   labels   = (const int*)  d_in[4];
    const float* word_emb = (const float*)d_in[5];
    const float* char_emb = (const float*)d_in[6];
    const float* Wc_fw    = (const float*)d_in[7];
    const float* bc_fw    = (const float*)d_in[8];
    const float* Wc_bw    = (const float*)d_in[9];
    const float* bc_bw    = (const float*)d_in[10];
    const float* Ww_fw    = (const float*)d_in[11];
    const float* bw_fw    = (const float*)d_in[12];
    const float* Ww_bw    = (const float*)d_in[13];
    const float* bw_bw    = (const float*)d_in[14];
    const float* W_proj   = (const float*)d_in[15];
    const float* b_proj   = (const float*)d_in[16];
    float* out = (float*)d_out;

    cudaFuncSetAttribute(k_char, cudaFuncAttributeMaxDynamicSharedMemorySize, C_SMEM);
    cudaFuncSetAttribute(k_xmma, cudaFuncAttributeMaxDynamicSharedMemorySize, X_SMEM);
    cudaFuncSetAttribute(k_wstep, cudaFuncAttributeMaxDynamicSharedMemorySize, W_SMEM);

    // order: k_char is the 4th launch (the one ncu captures)
    k_embed<<<(BT_ * 75 + 255) / 256, 256>>>(word_ids, word_emb);
    k_Wc2bf<<<(2 * GC_ * CKS + 255) / 256, 256>>>(Wc_fw, Wc_bw);
    k_zcv<<<dim3(NV_, 2), GC_>>>(char_emb, Wc_fw, bc_fw, Wc_bw, bc_bw);
    k_char<<<dim3(BT_ / 64, 2), 640, C_SMEM>>>(char_ids, word_len);
    k_sort<<<1, B_>>>(seq_len);
    k_permB<<<(2 * GW_ + 255) / 256, 256>>>(bw_fw, bw_bw);
    k_W2bf<<<(2 * GW_ * KP_ + 255) / 256, 256>>>(Ww_fw, Ww_bw);
    k_Wr2bf<<<(2 * GW_ * KR_ + 255) / 256, 256>>>(Ww_fw, Ww_bw);
    k_xmma<<<dim3(BT_ / 128, 10, 2), 384, X_SMEM>>>();
    k_wstep<<<dim3(15, 4, 2), 320, W_SMEM>>>(seq_len);
    k_final<<<1, 128>>>(labels, W_proj, b_proj, out);
}